// round 2
// baseline (speedup 1.0000x reference)
#include <cuda_runtime.h>
#include <cstdint>

#define HH    56
#define WW    56
#define HWSZ  3136            // 56*56
#define NPIX  50176           // 16*3136
#define XSTRB 401408          // 128*3136
#define NELEM 6422528         // 16*128*56*56

// ---------------- device scratch ----------------
__device__ float g_wq1[9 * 128 * 128];   // quantized weights [k][c][o]
__device__ float g_wq2[9 * 128 * 128];
__device__ float g_t0 [128 * NPIX];      // x transposed to [c][n]
__device__ float g_t1 [128 * NPIX];      // conv1 pre-BN output [c][n]
__device__ float g_t1r[128 * NPIX];      // relu(bn1(t1)) [c][n]
__device__ float g_t2 [128 * NPIX];      // conv2 pre-BN output [c][n]
__device__ float g_sum1[128], g_sumsq1[128];
__device__ float g_sum2[128], g_sumsq2[128];
__device__ float g_scale1[128], g_bias1[128];
__device__ float g_scale2[128], g_bias2[128];

// ---------------- f32x2 packed helpers (sm_103a) ----------------
static __device__ __forceinline__ uint64_t pack2(float a, float b) {
    uint64_t r; asm("mov.b64 %0,{%1,%2};" : "=l"(r) : "f"(a), "f"(b)); return r;
}
static __device__ __forceinline__ void unpack2(uint64_t v, float& a, float& b) {
    asm("mov.b64 {%0,%1},%2;" : "=f"(a), "=f"(b) : "l"(v));
}
static __device__ __forceinline__ uint64_t fma2(uint64_t a, uint64_t b, uint64_t c) {
    uint64_t d; asm("fma.rn.f32x2 %0,%1,%2,%3;" : "=l"(d) : "l"(a), "l"(b), "l"(c)); return d;
}

// ---------------- prep: quantize weights (LSQ 3-bit) + zero stats ----------------
__global__ void prep_kernel(const float* __restrict__ w1, const float* __restrict__ wa1,
                            const float* __restrict__ w2, const float* __restrict__ wa2)
{
    if (blockIdx.x == 0 && threadIdx.x < 128) {
        int t = threadIdx.x;
        g_sum1[t] = 0.f; g_sumsq1[t] = 0.f;
        g_sum2[t] = 0.f; g_sumsq2[t] = 0.f;
    }
    int idx = blockIdx.x * blockDim.x + threadIdx.x;
    if (idx < 2 * 9 * 128 * 128) {
        int layer = idx / (9 * 128 * 128);
        int r = idx - layer * (9 * 128 * 128);
        int k = r >> 14;
        int o = (r >> 7) & 127;
        int c = r & 127;
        const float* w  = layer ? w2  : w1;
        const float* wa = layer ? wa2 : wa1;
        float alpha = wa[k];
        float v = __fdiv_rn(w[(k << 14) + (o << 7) + c], alpha);
        v = fminf(fmaxf(v, -4.f), 3.f);
        float q = __fmul_rn(rintf(v), alpha);
        float* dst = layer ? g_wq2 : g_wq1;
        dst[(k << 14) + (c << 7) + o] = q;   // [k][c][o]
    }
}

// ---------------- transpose x: NCHW -> [c][n] ----------------
__global__ void transpose_x_kernel(const float* __restrict__ x)
{
    int bc = blockIdx.x;            // 16*128 planes
    int b = bc >> 7;
    int c = bc & 127;
    const float4* src = reinterpret_cast<const float4*>(x + b * XSTRB + c * HWSZ);
    float4* dst = reinterpret_cast<float4*>(g_t0 + c * NPIX + b * HWSZ);
    for (int i = threadIdx.x; i < HWSZ / 4; i += 256) dst[i] = src[i];
}

// ---------------- apply BN1 + ReLU: g_t1r = relu(bn1(g_t1)) ----------------
__global__ void bn_apply_kernel()
{
    int idx = blockIdx.x * 256 + threadIdx.x;   // float4 index over [c][n]
    if (idx >= NELEM / 4) return;
    int c = idx / (NPIX / 4);
    float s = g_scale1[c], bb = g_bias1[c];
    float4 v = reinterpret_cast<const float4*>(g_t1)[idx];
    v.x = fmaxf(fmaf(v.x, s, bb), 0.f);
    v.y = fmaxf(fmaf(v.y, s, bb), 0.f);
    v.z = fmaxf(fmaf(v.z, s, bb), 0.f);
    v.w = fmaxf(fmaf(v.w, s, bb), 0.f);
    reinterpret_cast<float4*>(g_t1r)[idx] = v;
}

// ---------------- conv: 9-tap split conv, psum LSQ(8b), f32x2 core ----------------
// Block tile: 64 n x 128 o. 256 threads, each 8o x 4n (o packed in f32x2 pairs).
template <int LAYER>
__global__ __launch_bounds__(256, 2)
void conv_kernel(const float* __restrict__ pa)
{
    __shared__ float sA[2][16][64];
    __shared__ float sB[2][16][128];
    __shared__ float sRed[2][128];

    const int t  = threadIdx.x;
    const int n0 = blockIdx.x << 6;
    const int nl = t & 63;
    const int nn = n0 + nl;
    const int b  = nn / HWSZ;
    const int hw = nn - b * HWSZ;
    const int h  = hw / WW;
    const int w  = hw - h * WW;
    const int caRow = t >> 6;       // 0..3
    const int og = t & 15;
    const int ng = t >> 4;
    const int bo = t & 127;
    const int bRow = t >> 7;        // 0..1

    const float* src = (LAYER == 1) ? g_t0  : g_t1r;
    const float* wq  = (LAYER == 1) ? g_wq1 : g_wq2;

    float ra[4];
    float rb[8];

    // ---- prefetch chunk q=0 (k=0: dh=-1, dw=-1) ----
    {
        const int hh = h - 1, ww2 = w - 1;
        const bool valid = (hh >= 0) && (ww2 >= 0);
        const int base = b * HWSZ + hh * WW + ww2;
#pragma unroll
        for (int i = 0; i < 4; i++) {
            int c = caRow + (i << 2);
            ra[i] = valid ? __ldg(src + c * NPIX + base) : 0.f;
        }
#pragma unroll
        for (int i = 0; i < 8; i++)
            rb[i] = __ldg(wq + ((bRow + (i << 1)) << 7) + bo);
    }
#pragma unroll
    for (int i = 0; i < 4; i++) sA[0][caRow + (i << 2)][nl] = ra[i];
#pragma unroll
    for (int i = 0; i < 8; i++) sB[0][bRow + (i << 1)][bo] = rb[i];
    __syncthreads();

    uint64_t psum[4][4];
#pragma unroll
    for (int i = 0; i < 4; i++)
#pragma unroll
        for (int j = 0; j < 4; j++) psum[i][j] = 0ull;

    float acc[8][4];
#pragma unroll
    for (int i = 0; i < 8; i++)
#pragma unroll
        for (int j = 0; j < 4; j++) acc[i][j] = 0.f;

    float pak = __ldg(pa);

#pragma unroll 1
    for (int q = 0; q < 72; q++) {
        const int buf = q & 1;

        // prefetch next chunk into registers (overlapped with compute)
        if (q < 71) {
            const int q1  = q + 1;
            const int k1  = q1 >> 3;
            const int cc1 = (q1 & 7) << 4;
            const int dh = k1 % 3 - 1;
            const int dw = k1 / 3 - 1;
            const int hh = h + dh, ww2 = w + dw;
            const bool valid = (hh >= 0) && (hh < HH) && (ww2 >= 0) && (ww2 < WW);
            const int base = b * HWSZ + hh * WW + ww2;
#pragma unroll
            for (int i = 0; i < 4; i++) {
                int c = cc1 + caRow + (i << 2);
                ra[i] = valid ? __ldg(src + c * NPIX + base) : 0.f;
            }
            const float* wk = wq + (k1 << 14) + (cc1 << 7);
#pragma unroll
            for (int i = 0; i < 8; i++)
                rb[i] = __ldg(wk + ((bRow + (i << 1)) << 7) + bo);
        }

        // ---- f32x2 FMA core: 16 c-steps ----
#pragma unroll
        for (int c = 0; c < 16; c++) {
            float4 av = *reinterpret_cast<const float4*>(&sA[buf][c][ng << 2]);
            const ulonglong2* pb = reinterpret_cast<const ulonglong2*>(&sB[buf][c][og << 3]);
            ulonglong2 bv0 = pb[0];
            ulonglong2 bv1 = pb[1];
            uint64_t a0 = pack2(av.x, av.x);
            uint64_t a1 = pack2(av.y, av.y);
            uint64_t a2 = pack2(av.z, av.z);
            uint64_t a3 = pack2(av.w, av.w);
            psum[0][0] = fma2(a0, bv0.x, psum[0][0]);
            psum[0][1] = fma2(a1, bv0.x, psum[0][1]);
            psum[0][2] = fma2(a2, bv0.x, psum[0][2]);
            psum[0][3] = fma2(a3, bv0.x, psum[0][3]);
            psum[1][0] = fma2(a0, bv0.y, psum[1][0]);
            psum[1][1] = fma2(a1, bv0.y, psum[1][1]);
            psum[1][2] = fma2(a2, bv0.y, psum[1][2]);
            psum[1][3] = fma2(a3, bv0.y, psum[1][3]);
            psum[2][0] = fma2(a0, bv1.x, psum[2][0]);
            psum[2][1] = fma2(a1, bv1.x, psum[2][1]);
            psum[2][2] = fma2(a2, bv1.x, psum[2][2]);
            psum[2][3] = fma2(a3, bv1.x, psum[2][3]);
            psum[3][0] = fma2(a0, bv1.y, psum[3][0]);
            psum[3][1] = fma2(a1, bv1.y, psum[3][1]);
            psum[3][2] = fma2(a2, bv1.y, psum[3][2]);
            psum[3][3] = fma2(a3, bv1.y, psum[3][3]);
        }

        // ---- per-tap partial-sum LSQ at tap boundary ----
        if ((q & 7) == 7) {
#pragma unroll
            for (int i2 = 0; i2 < 4; i2++)
#pragma unroll
                for (int j = 0; j < 4; j++) {
                    float p0, p1;
                    unpack2(psum[i2][j], p0, p1);
                    float v0 = __fdiv_rn(p0, pak);
                    v0 = fminf(fmaxf(v0, -128.f), 127.f);
                    acc[(i2 << 1) + 0][j] = __fadd_rn(acc[(i2 << 1) + 0][j], __fmul_rn(rintf(v0), pak));
                    float v1 = __fdiv_rn(p1, pak);
                    v1 = fminf(fmaxf(v1, -128.f), 127.f);
                    acc[(i2 << 1) + 1][j] = __fadd_rn(acc[(i2 << 1) + 1][j], __fmul_rn(rintf(v1), pak));
                    psum[i2][j] = 0ull;
                }
            if (q < 71) pak = __ldg(pa + ((q + 1) >> 3));
        }

        // ---- store prefetched regs into other buffer ----
        if (q < 71) {
#pragma unroll
            for (int i = 0; i < 4; i++) sA[buf ^ 1][caRow + (i << 2)][nl] = ra[i];
#pragma unroll
            for (int i = 0; i < 8; i++) sB[buf ^ 1][bRow + (i << 1)][bo] = rb[i];
            __syncthreads();
        }
    }

    // ---------------- epilogue: stores [c][n] + per-channel BN stats ----------------
    float* outT = (LAYER == 1) ? g_t1 : g_t2;
    float* ssum = (LAYER == 1) ? g_sum1 : g_sum2;
    float* ssq  = (LAYER == 1) ? g_sumsq1 : g_sumsq2;

    if (t < 128) { sRed[0][t] = 0.f; sRed[1][t] = 0.f; }
    __syncthreads();

#pragma unroll
    for (int i = 0; i < 8; i++) {
        int o = (og << 3) + i;
        float4 vv = make_float4(acc[i][0], acc[i][1], acc[i][2], acc[i][3]);
        *reinterpret_cast<float4*>(&outT[o * NPIX + n0 + (ng << 2)]) = vv;
        float s = acc[i][0] + acc[i][1] + acc[i][2] + acc[i][3];
        float qs = acc[i][0] * acc[i][0] + acc[i][1] * acc[i][1] +
                   acc[i][2] * acc[i][2] + acc[i][3] * acc[i][3];
        atomicAdd(&sRed[0][o], s);
        atomicAdd(&sRed[1][o], qs);
    }
    __syncthreads();
    if (t < 128) {
        atomicAdd(&ssum[t], sRed[0][t]);
        atomicAdd(&ssq[t],  sRed[1][t]);
    }
}

// ---------------- BN finalize ----------------
__global__ void bn_finalize_kernel(int layer, const float* __restrict__ g, const float* __restrict__ bv)
{
    int c = threadIdx.x;
    if (c < 128) {
        float sum = (layer == 1) ? g_sum1[c]   : g_sum2[c];
        float sq  = (layer == 1) ? g_sumsq1[c] : g_sumsq2[c];
        float m   = __fdiv_rn(sum, (float)NPIX);
        float var = fmaxf(__fdiv_rn(sq, (float)NPIX) - m * m, 0.f);
        float s   = __fdiv_rn(g[c], sqrtf(var + 1e-5f));
        float bb  = bv[c] - m * s;
        if (layer == 1) { g_scale1[c] = s; g_bias1[c] = bb; }
        else            { g_scale2[c] = s; g_bias2[c] = bb; }
    }
}

// ---------------- final: out = relu(bn2(t2) + identity), NCHW ----------------
__global__ void final_kernel(const float* __restrict__ x, float* __restrict__ out)
{
    int idx = blockIdx.x * blockDim.x + threadIdx.x;   // float4 index
    if (idx >= NELEM / 4) return;
    int e  = idx << 2;
    int b  = e / XSTRB;
    int r  = e - b * XSTRB;
    int c  = r / HWSZ;
    int hw = r - c * HWSZ;
    float4 xv = *reinterpret_cast<const float4*>(x + e);
    float4 tv = *reinterpret_cast<const float4*>(&g_t2[c * NPIX + b * HWSZ + hw]);
    float s = g_scale2[c], bb = g_bias2[c];
    float4 ov;
    ov.x = fmaxf(fmaf(tv.x, s, bb) + xv.x, 0.f);
    ov.y = fmaxf(fmaf(tv.y, s, bb) + xv.y, 0.f);
    ov.z = fmaxf(fmaf(tv.z, s, bb) + xv.z, 0.f);
    ov.w = fmaxf(fmaf(tv.w, s, bb) + xv.w, 0.f);
    *reinterpret_cast<float4*>(out + e) = ov;
}

// ---------------- launch ----------------
extern "C" void kernel_launch(void* const* d_in, const int* in_sizes, int n_in,
                              void* d_out, int out_size)
{
    const float* x   = (const float*)d_in[0];
    const float* w1  = (const float*)d_in[1];
    const float* wa1 = (const float*)d_in[2];
    const float* pa1 = (const float*)d_in[3];
    const float* g1  = (const float*)d_in[4];
    const float* b1  = (const float*)d_in[5];
    const float* w2  = (const float*)d_in[6];
    const float* wa2 = (const float*)d_in[7];
    const float* pa2 = (const float*)d_in[8];
    const float* g2  = (const float*)d_in[9];
    const float* b2  = (const float*)d_in[10];
    float* out = (float*)d_out;

    (void)in_sizes; (void)n_in; (void)out_size;

    prep_kernel<<<1152, 256>>>(w1, wa1, w2, wa2);
    transpose_x_kernel<<<2048, 256>>>(x);
    conv_kernel<1><<<NPIX / 64, 256>>>(pa1);
    bn_finalize_kernel<<<1, 128>>>(1, g1, b1);
    bn_apply_kernel<<<NELEM / 4 / 256, 256>>>();
    conv_kernel<2><<<NPIX / 64, 256>>>(pa2);
    bn_finalize_kernel<<<1, 128>>>(2, g2, b2);
    final_kernel<<<NELEM / 4 / 256, 256>>>(x, out);
}

// round 3
// speedup vs baseline: 1.0555x; 1.0555x over previous
#include <cuda_runtime.h>
#include <cstdint>

#define HH    56
#define WW    56
#define HWSZ  3136            // 56*56
#define NPIX  50176           // 16*3136
#define XSTRB 401408          // 128*3136
#define NELEM 6422528         // 16*128*56*56

// ---------------- device scratch ----------------
__device__ float g_wq1[9 * 128 * 128];   // quantized weights [k][c][o]
__device__ float g_wq2[9 * 128 * 128];
__device__ float g_t0 [128 * NPIX];      // x transposed to [c][n]
__device__ float g_t1 [128 * NPIX];      // conv1 pre-BN output [c][n]
__device__ float g_t1r[128 * NPIX];      // relu(bn1(t1)) [c][n]
__device__ float g_t2 [128 * NPIX];      // conv2 pre-BN output [c][n]
__device__ float g_sum1[128], g_sumsq1[128];
__device__ float g_sum2[128], g_sumsq2[128];
__device__ float g_scale1[128], g_bias1[128];
__device__ float g_scale2[128], g_bias2[128];

// ---------------- f32x2 packed helpers (sm_103a) ----------------
static __device__ __forceinline__ uint64_t pack2(float a, float b) {
    uint64_t r; asm("mov.b64 %0,{%1,%2};" : "=l"(r) : "f"(a), "f"(b)); return r;
}
static __device__ __forceinline__ void unpack2(uint64_t v, float& a, float& b) {
    asm("mov.b64 {%0,%1},%2;" : "=f"(a), "=f"(b) : "l"(v));
}
static __device__ __forceinline__ uint64_t fma2(uint64_t a, uint64_t b, uint64_t c) {
    uint64_t d; asm("fma.rn.f32x2 %0,%1,%2,%3;" : "=l"(d) : "l"(a), "l"(b), "l"(c)); return d;
}

// ---------------- prep: quantize weights (LSQ 3-bit) + zero stats ----------------
__global__ void prep_kernel(const float* __restrict__ w1, const float* __restrict__ wa1,
                            const float* __restrict__ w2, const float* __restrict__ wa2)
{
    if (blockIdx.x == 0 && threadIdx.x < 128) {
        int t = threadIdx.x;
        g_sum1[t] = 0.f; g_sumsq1[t] = 0.f;
        g_sum2[t] = 0.f; g_sumsq2[t] = 0.f;
    }
    int idx = blockIdx.x * blockDim.x + threadIdx.x;
    if (idx < 2 * 9 * 128 * 128) {
        int layer = idx / (9 * 128 * 128);
        int r = idx - layer * (9 * 128 * 128);
        int k = r >> 14;
        int o = (r >> 7) & 127;
        int c = r & 127;
        const float* w  = layer ? w2  : w1;
        const float* wa = layer ? wa2 : wa1;
        float alpha = wa[k];
        float v = __fdiv_rn(w[(k << 14) + (o << 7) + c], alpha);
        v = fminf(fmaxf(v, -4.f), 3.f);
        float q = __fmul_rn(rintf(v), alpha);
        float* dst = layer ? g_wq2 : g_wq1;
        dst[(k << 14) + (c << 7) + o] = q;   // [k][c][o]
    }
}

// ---------------- transpose x: NCHW -> [c][n] ----------------
__global__ void transpose_x_kernel(const float* __restrict__ x)
{
    int bc = blockIdx.x;            // 16*128 planes
    int b = bc >> 7;
    int c = bc & 127;
    const float4* src = reinterpret_cast<const float4*>(x + b * XSTRB + c * HWSZ);
    float4* dst = reinterpret_cast<float4*>(g_t0 + c * NPIX + b * HWSZ);
    for (int i = threadIdx.x; i < HWSZ / 4; i += 256) dst[i] = src[i];
}

// ---------------- apply BN1 + ReLU: g_t1r = relu(bn1(g_t1)) ----------------
__global__ void bn_apply_kernel()
{
    int idx = blockIdx.x * 256 + threadIdx.x;   // float4 index over [c][n]
    if (idx >= NELEM / 4) return;
    int c = idx / (NPIX / 4);
    float s = g_scale1[c], bb = g_bias1[c];
    float4 v = reinterpret_cast<const float4*>(g_t1)[idx];
    v.x = fmaxf(fmaf(v.x, s, bb), 0.f);
    v.y = fmaxf(fmaf(v.y, s, bb), 0.f);
    v.z = fmaxf(fmaf(v.z, s, bb), 0.f);
    v.w = fmaxf(fmaf(v.w, s, bb), 0.f);
    reinterpret_cast<float4*>(g_t1r)[idx] = v;
}

// ---------------- conv: 9-tap split conv, psum LSQ(8b), f32x2 core ----------------
// Block tile: 64 n x 128 o. 256 threads, each 8o x 4n (o packed in f32x2 pairs).
template <int LAYER>
__global__ __launch_bounds__(256, 2)
void conv_kernel(const float* __restrict__ pa)
{
    __shared__ float sA[2][16][64];
    __shared__ float sB[2][16][128];
    __shared__ float sRed[2][128];

    const int t  = threadIdx.x;
    const int n0 = blockIdx.x << 6;
    const int nl = t & 63;
    const int nn = n0 + nl;
    const int b  = nn / HWSZ;
    const int hw = nn - b * HWSZ;
    const int h  = hw / WW;
    const int w  = hw - h * WW;
    const int caRow = t >> 6;       // 0..3
    const int og = t & 15;
    const int ng = t >> 4;
    const int bo = t & 127;
    const int bRow = t >> 7;        // 0..1

    const float* src = (LAYER == 1) ? g_t0  : g_t1r;
    const float* wq  = (LAYER == 1) ? g_wq1 : g_wq2;

    float ra[4];
    float rb[8];

    // ---- prefetch chunk q=0 (k=0: dh=-1, dw=-1) ----
    {
        const int hh = h - 1, ww2 = w - 1;
        const bool valid = (hh >= 0) && (ww2 >= 0);
        const int base = b * HWSZ + hh * WW + ww2;
#pragma unroll
        for (int i = 0; i < 4; i++) {
            int c = caRow + (i << 2);
            ra[i] = valid ? __ldg(src + c * NPIX + base) : 0.f;
        }
#pragma unroll
        for (int i = 0; i < 8; i++)
            rb[i] = __ldg(wq + ((bRow + (i << 1)) << 7) + bo);
    }
#pragma unroll
    for (int i = 0; i < 4; i++) sA[0][caRow + (i << 2)][nl] = ra[i];
#pragma unroll
    for (int i = 0; i < 8; i++) sB[0][bRow + (i << 1)][bo] = rb[i];
    __syncthreads();

    uint64_t psum[4][4];
#pragma unroll
    for (int i = 0; i < 4; i++)
#pragma unroll
        for (int j = 0; j < 4; j++) psum[i][j] = 0ull;

    float acc[8][4];
#pragma unroll
    for (int i = 0; i < 8; i++)
#pragma unroll
        for (int j = 0; j < 4; j++) acc[i][j] = 0.f;

    float pak = __ldg(pa);

#pragma unroll 1
    for (int q = 0; q < 72; q++) {
        const int buf = q & 1;

        // prefetch next chunk into registers (overlapped with compute)
        if (q < 71) {
            const int q1  = q + 1;
            const int k1  = q1 >> 3;
            const int cc1 = (q1 & 7) << 4;
            const int dh = k1 % 3 - 1;
            const int dw = k1 / 3 - 1;
            const int hh = h + dh, ww2 = w + dw;
            const bool valid = (hh >= 0) && (hh < HH) && (ww2 >= 0) && (ww2 < WW);
            const int base = b * HWSZ + hh * WW + ww2;
#pragma unroll
            for (int i = 0; i < 4; i++) {
                int c = cc1 + caRow + (i << 2);
                ra[i] = valid ? __ldg(src + c * NPIX + base) : 0.f;
            }
            const float* wk = wq + (k1 << 14) + (cc1 << 7);
#pragma unroll
            for (int i = 0; i < 8; i++)
                rb[i] = __ldg(wk + ((bRow + (i << 1)) << 7) + bo);
        }

        // ---- f32x2 FMA core: 16 c-steps ----
#pragma unroll
        for (int c = 0; c < 16; c++) {
            float4 av = *reinterpret_cast<const float4*>(&sA[buf][c][ng << 2]);
            const ulonglong2* pb = reinterpret_cast<const ulonglong2*>(&sB[buf][c][og << 3]);
            ulonglong2 bv0 = pb[0];
            ulonglong2 bv1 = pb[1];
            uint64_t a0 = pack2(av.x, av.x);
            uint64_t a1 = pack2(av.y, av.y);
            uint64_t a2 = pack2(av.z, av.z);
            uint64_t a3 = pack2(av.w, av.w);
            psum[0][0] = fma2(a0, bv0.x, psum[0][0]);
            psum[0][1] = fma2(a1, bv0.x, psum[0][1]);
            psum[0][2] = fma2(a2, bv0.x, psum[0][2]);
            psum[0][3] = fma2(a3, bv0.x, psum[0][3]);
            psum[1][0] = fma2(a0, bv0.y, psum[1][0]);
            psum[1][1] = fma2(a1, bv0.y, psum[1][1]);
            psum[1][2] = fma2(a2, bv0.y, psum[1][2]);
            psum[1][3] = fma2(a3, bv0.y, psum[1][3]);
            psum[2][0] = fma2(a0, bv1.x, psum[2][0]);
            psum[2][1] = fma2(a1, bv1.x, psum[2][1]);
            psum[2][2] = fma2(a2, bv1.x, psum[2][2]);
            psum[2][3] = fma2(a3, bv1.x, psum[2][3]);
            psum[3][0] = fma2(a0, bv1.y, psum[3][0]);
            psum[3][1] = fma2(a1, bv1.y, psum[3][1]);
            psum[3][2] = fma2(a2, bv1.y, psum[3][2]);
            psum[3][3] = fma2(a3, bv1.y, psum[3][3]);
        }

        // ---- per-tap partial-sum LSQ at tap boundary ----
        if ((q & 7) == 7) {
#pragma unroll
            for (int i2 = 0; i2 < 4; i2++)
#pragma unroll
                for (int j = 0; j < 4; j++) {
                    float p0, p1;
                    unpack2(psum[i2][j], p0, p1);
                    float v0 = __fdiv_rn(p0, pak);
                    v0 = fminf(fmaxf(v0, -128.f), 127.f);
                    acc[(i2 << 1) + 0][j] = __fadd_rn(acc[(i2 << 1) + 0][j], __fmul_rn(rintf(v0), pak));
                    float v1 = __fdiv_rn(p1, pak);
                    v1 = fminf(fmaxf(v1, -128.f), 127.f);
                    acc[(i2 << 1) + 1][j] = __fadd_rn(acc[(i2 << 1) + 1][j], __fmul_rn(rintf(v1), pak));
                    psum[i2][j] = 0ull;
                }
            if (q < 71) pak = __ldg(pa + ((q + 1) >> 3));
        }

        // ---- store prefetched regs into other buffer ----
        if (q < 71) {
#pragma unroll
            for (int i = 0; i < 4; i++) sA[buf ^ 1][caRow + (i << 2)][nl] = ra[i];
#pragma unroll
            for (int i = 0; i < 8; i++) sB[buf ^ 1][bRow + (i << 1)][bo] = rb[i];
            __syncthreads();
        }
    }

    // ---------------- epilogue: stores [c][n] + per-channel BN stats ----------------
    float* outT = (LAYER == 1) ? g_t1 : g_t2;
    float* ssum = (LAYER == 1) ? g_sum1 : g_sum2;
    float* ssq  = (LAYER == 1) ? g_sumsq1 : g_sumsq2;

    if (t < 128) { sRed[0][t] = 0.f; sRed[1][t] = 0.f; }
    __syncthreads();

#pragma unroll
    for (int i = 0; i < 8; i++) {
        int o = (og << 3) + i;
        float4 vv = make_float4(acc[i][0], acc[i][1], acc[i][2], acc[i][3]);
        *reinterpret_cast<float4*>(&outT[o * NPIX + n0 + (ng << 2)]) = vv;
        float s = acc[i][0] + acc[i][1] + acc[i][2] + acc[i][3];
        float qs = acc[i][0] * acc[i][0] + acc[i][1] * acc[i][1] +
                   acc[i][2] * acc[i][2] + acc[i][3] * acc[i][3];
        atomicAdd(&sRed[0][o], s);
        atomicAdd(&sRed[1][o], qs);
    }
    __syncthreads();
    if (t < 128) {
        atomicAdd(&ssum[t], sRed[0][t]);
        atomicAdd(&ssq[t],  sRed[1][t]);
    }
}

// ---------------- BN finalize ----------------
__global__ void bn_finalize_kernel(int layer, const float* __restrict__ g, const float* __restrict__ bv)
{
    int c = threadIdx.x;
    if (c < 128) {
        float sum = (layer == 1) ? g_sum1[c]   : g_sum2[c];
        float sq  = (layer == 1) ? g_sumsq1[c] : g_sumsq2[c];
        float m   = __fdiv_rn(sum, (float)NPIX);
        float var = fmaxf(__fdiv_rn(sq, (float)NPIX) - m * m, 0.f);
        float s   = __fdiv_rn(g[c], sqrtf(var + 1e-5f));
        float bb  = bv[c] - m * s;
        if (layer == 1) { g_scale1[c] = s; g_bias1[c] = bb; }
        else            { g_scale2[c] = s; g_bias2[c] = bb; }
    }
}

// ---------------- final: out = relu(bn2(t2) + identity), NCHW ----------------
__global__ void final_kernel(const float* __restrict__ x, float* __restrict__ out)
{
    int idx = blockIdx.x * blockDim.x + threadIdx.x;   // float4 index
    if (idx >= NELEM / 4) return;
    int e  = idx << 2;
    int b  = e / XSTRB;
    int r  = e - b * XSTRB;
    int c  = r / HWSZ;
    int hw = r - c * HWSZ;
    float4 xv = *reinterpret_cast<const float4*>(x + e);
    float4 tv = *reinterpret_cast<const float4*>(&g_t2[c * NPIX + b * HWSZ + hw]);
    float s = g_scale2[c], bb = g_bias2[c];
    float4 ov;
    ov.x = fmaxf(fmaf(tv.x, s, bb) + xv.x, 0.f);
    ov.y = fmaxf(fmaf(tv.y, s, bb) + xv.y, 0.f);
    ov.z = fmaxf(fmaf(tv.z, s, bb) + xv.z, 0.f);
    ov.w = fmaxf(fmaf(tv.w, s, bb) + xv.w, 0.f);
    *reinterpret_cast<float4*>(out + e) = ov;
}

// ---------------- launch ----------------
extern "C" void kernel_launch(void* const* d_in, const int* in_sizes, int n_in,
                              void* d_out, int out_size)
{
    const float* x   = (const float*)d_in[0];
    const float* w1  = (const float*)d_in[1];
    const float* wa1 = (const float*)d_in[2];
    const float* pa1 = (const float*)d_in[3];
    const float* g1  = (const float*)d_in[4];
    const float* b1  = (const float*)d_in[5];
    const float* w2  = (const float*)d_in[6];
    const float* wa2 = (const float*)d_in[7];
    const float* pa2 = (const float*)d_in[8];
    const float* g2  = (const float*)d_in[9];
    const float* b2  = (const float*)d_in[10];
    float* out = (float*)d_out;

    (void)in_sizes; (void)n_in; (void)out_size;

    prep_kernel<<<1152, 256>>>(w1, wa1, w2, wa2);
    transpose_x_kernel<<<2048, 256>>>(x);
    conv_kernel<1><<<NPIX / 64, 256>>>(pa1);
    bn_finalize_kernel<<<1, 128>>>(1, g1, b1);
    bn_apply_kernel<<<NELEM / 4 / 256, 256>>>();
    conv_kernel<2><<<NPIX / 64, 256>>>(pa2);
    bn_finalize_kernel<<<1, 128>>>(2, g2, b2);
    final_kernel<<<NELEM / 4 / 256, 256>>>(x, out);
}